// round 3
// baseline (speedup 1.0000x reference)
#include <cuda_runtime.h>
#include <cstdint>

#define N_   256
#define C_   2048
#define HW_  128
#define K_   13

typedef unsigned long long ull;

// ---------- packed f32x2 helpers (sm_103a) ----------
__device__ __forceinline__ ull pack2(float lo, float hi) {
    ull r; asm("mov.b64 %0, {%1,%2};" : "=l"(r) : "f"(lo), "f"(hi)); return r;
}
__device__ __forceinline__ void unpack2(ull v, float& lo, float& hi) {
    asm("mov.b64 {%0,%1}, %2;" : "=f"(lo), "=f"(hi) : "l"(v));
}
__device__ __forceinline__ ull fma2(ull a, ull b, ull c) {
    ull d; asm("fma.rn.f32x2 %0, %1, %2, %3;" : "=l"(d) : "l"(a), "l"(b), "l"(c)); return d;
}
__device__ __forceinline__ ull add2(ull a, ull b) {
    ull d; asm("add.rn.f32x2 %0, %1, %2;" : "=l"(d) : "l"(a), "l"(b)); return d;
}

// Fused: local[n,k,c] = sum_hw scoremap[n,k,hw]*feat[n,c,hw]
//        glob[n,c]    = mean_hw feat + max_hw feat
// Output feat_vecs [N,14,C] row-major, conf [N,14] appended after it.
//
// Block: 128 threads. Lane octet (8 lanes) covers one 128B line of a channel
// row per LDG.128 (perfect coalescing: 4 lines per warp LDG, the minimum).
// Each thread owns 4 channels and 1/8 of the 128 spatial positions; 13
// packed-f32x2 accumulators per channel; 3-step octet butterfly at the end.
__global__ void __launch_bounds__(128)
fused_local_global_kernel(const float* __restrict__ feat,
                          const float* __restrict__ scoremap,
                          float* __restrict__ out)
{
    __shared__ __align__(16) float s_s[K_ * HW_];   // scoremap[n] : 13 x 128

    const int n  = blockIdx.y;
    const int c0 = blockIdx.x * 64;                 // 64 channels per block
    const int tid = threadIdx.x;

    // stage scoremap[n] (6.5 KB) into smem
    {
        const float4* src = reinterpret_cast<const float4*>(scoremap + (size_t)n * K_ * HW_);
        float4* dst = reinterpret_cast<float4*>(s_s);
        for (int i = tid; i < K_ * HW_ / 4; i += 128) dst[i] = src[i];
    }
    __syncthreads();

    const int o = tid & 7;        // lane within octet -> spatial sub-slice
    const int g = tid >> 3;       // octet index within block (0..15)
    const int cbase = c0 + g * 4; // this thread's 4 channels: cbase..cbase+3

    const float* fb = feat + ((size_t)n * C_ + cbase) * HW_;

    ull  acc[4][K_];
    ull  sum2[4];
    float vmax[4];
    #pragma unroll
    for (int ch = 0; ch < 4; ch++) {
        #pragma unroll
        for (int k = 0; k < K_; k++) acc[ch][k] = 0ull;   // (+0.0f, +0.0f)
        sum2[ch] = 0ull;
        vmax[ch] = -3.402823466e+38f;
    }

    #pragma unroll
    for (int j = 0; j < 4; j++) {
        const int p = j * 32 + o * 4;     // this lane's 4 positions this step

        float4 f[4];
        #pragma unroll
        for (int ch = 0; ch < 4; ch++)
            f[ch] = *reinterpret_cast<const float4*>(fb + ch * HW_ + p);

        ull fxy[4], fzw[4];
        #pragma unroll
        for (int ch = 0; ch < 4; ch++) {
            fxy[ch] = pack2(f[ch].x, f[ch].y);
            fzw[ch] = pack2(f[ch].z, f[ch].w);
            sum2[ch] = add2(sum2[ch], add2(fxy[ch], fzw[ch]));
            vmax[ch] = fmaxf(vmax[ch], fmaxf(fmaxf(f[ch].x, f[ch].y),
                                             fmaxf(f[ch].z, f[ch].w)));
        }

        #pragma unroll
        for (int k = 0; k < K_; k++) {
            const ull sA = *reinterpret_cast<const ull*>(s_s + k * HW_ + p);
            const ull sB = *reinterpret_cast<const ull*>(s_s + k * HW_ + p + 2);
            #pragma unroll
            for (int ch = 0; ch < 4; ch++) {
                acc[ch][k] = fma2(fxy[ch], sA, acc[ch][k]);
                acc[ch][k] = fma2(fzw[ch], sB, acc[ch][k]);
            }
        }
    }

    // octet reduction (lanes differ in lane-id bits 0..2) + writeout
    const unsigned mask = 0xffffffffu;
    #pragma unroll
    for (int ch = 0; ch < 4; ch++) {
        float res[K_];
        #pragma unroll
        for (int k = 0; k < K_; k++) {
            float lo, hi; unpack2(acc[ch][k], lo, hi);
            res[k] = lo + hi;
        }
        float lo, hi; unpack2(sum2[ch], lo, hi);
        float sm = lo + hi;
        float mx = vmax[ch];

        #pragma unroll
        for (int d = 1; d < 8; d <<= 1) {
            #pragma unroll
            for (int k = 0; k < K_; k++)
                res[k] += __shfl_xor_sync(mask, res[k], d);
            sm += __shfl_xor_sync(mask, sm, d);
            mx  = fmaxf(mx, __shfl_xor_sync(mask, mx, d));
        }

        if (o == 0) {
            const int c = cbase + ch;
            float* ob = out + (size_t)n * 14 * C_ + c;
            #pragma unroll
            for (int k = 0; k < K_; k++) ob[(size_t)k * C_] = res[k];
            ob[(size_t)13 * C_] = sm * (1.0f / 128.0f) + mx;
        }
    }
}

// conf: L1-normalize the 13 keypoint confidences per n, append 1.0.
// Writes only if the harness buffer actually has room for the conf slice.
__global__ void conf_kernel(const float* __restrict__ kc, float* __restrict__ out,
                            int out_size)
{
    const int n = blockIdx.x * blockDim.x + threadIdx.x;
    if (n >= N_) return;
    const long long base = (long long)N_ * 14 * C_ + (long long)n * 14;
    if (base + 14 > (long long)out_size) return;
    float v[K_];
    float s = 0.0f;
    #pragma unroll
    for (int k = 0; k < K_; k++) { v[k] = kc[n * K_ + k]; s += fabsf(v[k]); }
    const float inv = 1.0f / fmaxf(s, 1e-12f);
    float* ob = out + base;
    #pragma unroll
    for (int k = 0; k < K_; k++) ob[k] = v[k] * inv;
    ob[13] = 1.0f;
}

extern "C" void kernel_launch(void* const* d_in, const int* in_sizes, int n_in,
                              void* d_out, int out_size)
{
    const float* feat = (const float*)d_in[0];           // [256,2048,16,8]
    const float* sc   = (const float*)d_in[1];           // [256,13,16,8]
    const float* kc   = (const float*)d_in[2];           // [256,13]
    float* out = (float*)d_out;

    dim3 grid(C_ / 64, N_);                               // 32 x 256 blocks
    fused_local_global_kernel<<<grid, 128>>>(feat, sc, out);
    conf_kernel<<<1, 256>>>(kc, out, out_size);
}

// round 7
// speedup vs baseline: 1.1335x; 1.1335x over previous
#include <cuda_runtime.h>
#include <cstdint>

#define N_   256
#define C_   2048
#define HW_  128
#define K_   13

typedef unsigned long long ull;

// ---------- packed f32x2 helpers (sm_103a) ----------
__device__ __forceinline__ ull pack2(float lo, float hi) {
    ull r; asm("mov.b64 %0, {%1,%2};" : "=l"(r) : "f"(lo), "f"(hi)); return r;
}
__device__ __forceinline__ void unpack2(ull v, float& lo, float& hi) {
    asm("mov.b64 {%0,%1}, %2;" : "=f"(lo), "=f"(hi) : "l"(v));
}
__device__ __forceinline__ ull fma2(ull a, ull b, ull c) {
    ull d; asm("fma.rn.f32x2 %0, %1, %2, %3;" : "=l"(d) : "l"(a), "l"(b), "l"(c)); return d;
}
__device__ __forceinline__ ull add2(ull a, ull b) {
    ull d; asm("add.rn.f32x2 %0, %1, %2;" : "=l"(d) : "l"(a), "l"(b)); return d;
}

// Fused: local[n,k,c] = sum_hw scoremap[n,k,hw]*feat[n,c,hw]
//        glob[n,c]    = mean_hw feat + max_hw feat
//        conf[n,:]    = [L1norm(kc[n]), 1.0]   (warp 0 of blockIdx.x==0 blocks)
// Output: feat_vecs [N,14,C] row-major, then conf [N,14].
//
// 2 channels per thread (52 accumulator regs -> no spill), octet of 8 lanes
// covers one 128B line per channel-row LDG.128 (minimum wavefronts).
__global__ void __launch_bounds__(128)
fused_local_global_kernel(const float* __restrict__ feat,
                          const float* __restrict__ scoremap,
                          const float* __restrict__ kc,
                          float* __restrict__ out,
                          int out_size)
{
    __shared__ __align__(16) float s_s[K_ * HW_];   // scoremap[n] : 13 x 128

    const int n   = blockIdx.y;
    const int c0  = blockIdx.x * 32;                // 32 channels per block
    const int tid = threadIdx.x;

    // conf for this n. FULL warp participates in the shuffle (legal mask);
    // lanes >= 13 contribute 0 to the L1 sum.
    if (blockIdx.x == 0 && tid < 32) {
        const float v = (tid < K_) ? kc[n * K_ + tid] : 0.0f;
        float s = fabsf(v);
        #pragma unroll
        for (int d = 1; d < 32; d <<= 1)
            s += __shfl_xor_sync(0xffffffffu, s, d);
        const float inv = 1.0f / fmaxf(s, 1e-12f);
        const long long base = (long long)N_ * 14 * C_ + (long long)n * 14;
        if (tid < 14 && base + 14 <= (long long)out_size)
            out[base + tid] = (tid < K_) ? v * inv : 1.0f;
    }

    // stage scoremap[n] (6.5 KB) into smem
    {
        const float4* src = reinterpret_cast<const float4*>(scoremap + (size_t)n * K_ * HW_);
        float4* dst = reinterpret_cast<float4*>(s_s);
        for (int i = tid; i < K_ * HW_ / 4; i += 128) dst[i] = src[i];
    }
    __syncthreads();

    const int o = tid & 7;        // lane within octet -> spatial sub-slice
    const int g = tid >> 3;       // octet index within block (0..15)
    const int cbase = c0 + g * 2; // this thread's 2 channels

    const float* fb = feat + ((size_t)n * C_ + cbase) * HW_;

    ull  acc[2][K_];
    ull  sum2[2];
    float vmax[2];
    #pragma unroll
    for (int ch = 0; ch < 2; ch++) {
        #pragma unroll
        for (int k = 0; k < K_; k++) acc[ch][k] = 0ull;   // (+0.0f, +0.0f)
        sum2[ch] = 0ull;
        vmax[ch] = -3.402823466e+38f;
    }

    #pragma unroll
    for (int j = 0; j < 4; j++) {
        const int p = j * 32 + o * 4;     // this lane's 4 positions this step

        float4 f[2];
        #pragma unroll
        for (int ch = 0; ch < 2; ch++)
            f[ch] = *reinterpret_cast<const float4*>(fb + ch * HW_ + p);

        ull fxy[2], fzw[2];
        #pragma unroll
        for (int ch = 0; ch < 2; ch++) {
            fxy[ch] = pack2(f[ch].x, f[ch].y);
            fzw[ch] = pack2(f[ch].z, f[ch].w);
            sum2[ch] = add2(sum2[ch], add2(fxy[ch], fzw[ch]));
            vmax[ch] = fmaxf(vmax[ch], fmaxf(fmaxf(f[ch].x, f[ch].y),
                                             fmaxf(f[ch].z, f[ch].w)));
        }

        #pragma unroll
        for (int k = 0; k < K_; k++) {
            const ull sA = *reinterpret_cast<const ull*>(s_s + k * HW_ + p);
            const ull sB = *reinterpret_cast<const ull*>(s_s + k * HW_ + p + 2);
            #pragma unroll
            for (int ch = 0; ch < 2; ch++) {
                acc[ch][k] = fma2(fxy[ch], sA, acc[ch][k]);
                acc[ch][k] = fma2(fzw[ch], sB, acc[ch][k]);
            }
        }
    }

    // octet reduction (lanes differ in lane-id bits 0..2) + writeout
    const unsigned mask = 0xffffffffu;
    #pragma unroll
    for (int ch = 0; ch < 2; ch++) {
        float res[K_];
        #pragma unroll
        for (int k = 0; k < K_; k++) {
            float lo, hi; unpack2(acc[ch][k], lo, hi);
            res[k] = lo + hi;
        }
        float lo, hi; unpack2(sum2[ch], lo, hi);
        float sm = lo + hi;
        float mx = vmax[ch];

        #pragma unroll
        for (int d = 1; d < 8; d <<= 1) {
            #pragma unroll
            for (int k = 0; k < K_; k++)
                res[k] += __shfl_xor_sync(mask, res[k], d);
            sm += __shfl_xor_sync(mask, sm, d);
            mx  = fmaxf(mx, __shfl_xor_sync(mask, mx, d));
        }

        if (o == 0) {
            const int c = cbase + ch;
            float* ob = out + (size_t)n * 14 * C_ + c;
            #pragma unroll
            for (int k = 0; k < K_; k++) ob[(size_t)k * C_] = res[k];
            ob[(size_t)13 * C_] = sm * (1.0f / 128.0f) + mx;
        }
    }
}

extern "C" void kernel_launch(void* const* d_in, const int* in_sizes, int n_in,
                              void* d_out, int out_size)
{
    const float* feat = (const float*)d_in[0];           // [256,2048,16,8]
    const float* sc   = (const float*)d_in[1];           // [256,13,16,8]
    const float* kc   = (const float*)d_in[2];           // [256,13]
    float* out = (float*)d_out;

    dim3 grid(C_ / 32, N_);                               // 64 x 256 blocks
    fused_local_global_kernel<<<grid, 128>>>(feat, sc, kc, out, out_size);
}

// round 8
// speedup vs baseline: 1.3064x; 1.1525x over previous
#include <cuda_runtime.h>
#include <cstdint>

#define N_   256
#define C_   2048
#define HW_  128
#define K_   13

typedef unsigned long long ull;

// ---------- packed f32x2 helpers (sm_103a) ----------
__device__ __forceinline__ ull pack2(float lo, float hi) {
    ull r; asm("mov.b64 %0, {%1,%2};" : "=l"(r) : "f"(lo), "f"(hi)); return r;
}
__device__ __forceinline__ void unpack2(ull v, float& lo, float& hi) {
    asm("mov.b64 {%0,%1}, %2;" : "=f"(lo), "=f"(hi) : "l"(v));
}
__device__ __forceinline__ ull fma2(ull a, ull b, ull c) {
    ull d; asm("fma.rn.f32x2 %0, %1, %2, %3;" : "=l"(d) : "l"(a), "l"(b), "l"(c)); return d;
}
__device__ __forceinline__ ull add2(ull a, ull b) {
    ull d; asm("add.rn.f32x2 %0, %1, %2;" : "=l"(d) : "l"(a), "l"(b)); return d;
}

// Fused: local[n,k,c] = sum_hw scoremap[n,k,hw]*feat[n,c,hw]
//        glob[n,c]    = mean_hw feat + max_hw feat
//        conf[n,:]    = [L1norm(kc[n]), 1.0]   (warp 0 of blockIdx.x==0 blocks)
// Output: feat_vecs [N,14,C] row-major, then conf [N,14].
//
// 2 channels per thread; octet of 8 lanes covers one 128B line per
// channel-row LDG.128. Scoremap pair (sA,sB) fetched with ONE LDS.128
// (16B contiguous, 8 distinct addrs x 4-way broadcast = conflict-free).
// launch_bounds(128,6): cap regs ~85 so 6 CTAs/SM (24 warps) fit.
__global__ void __launch_bounds__(128, 6)
fused_local_global_kernel(const float* __restrict__ feat,
                          const float* __restrict__ scoremap,
                          const float* __restrict__ kc,
                          float* __restrict__ out,
                          int out_size)
{
    __shared__ __align__(16) float s_s[K_ * HW_];   // scoremap[n] : 13 x 128

    const int n   = blockIdx.y;
    const int c0  = blockIdx.x * 32;                // 32 channels per block
    const int tid = threadIdx.x;

    // conf for this n. Full warp participates in shuffle (legal mask);
    // lanes >= 13 contribute 0 to the L1 sum.
    if (blockIdx.x == 0 && tid < 32) {
        const float v = (tid < K_) ? kc[n * K_ + tid] : 0.0f;
        float s = fabsf(v);
        #pragma unroll
        for (int d = 1; d < 32; d <<= 1)
            s += __shfl_xor_sync(0xffffffffu, s, d);
        const float inv = 1.0f / fmaxf(s, 1e-12f);
        const long long base = (long long)N_ * 14 * C_ + (long long)n * 14;
        if (tid < 14 && base + 14 <= (long long)out_size)
            out[base + tid] = (tid < K_) ? v * inv : 1.0f;
    }

    // stage scoremap[n] (6.5 KB) into smem
    {
        const float4* src = reinterpret_cast<const float4*>(scoremap + (size_t)n * K_ * HW_);
        float4* dst = reinterpret_cast<float4*>(s_s);
        for (int i = tid; i < K_ * HW_ / 4; i += 128) dst[i] = src[i];
    }
    __syncthreads();

    const int o = tid & 7;        // lane within octet -> spatial sub-slice
    const int g = tid >> 3;       // octet index within block (0..15)
    const int cbase = c0 + g * 2; // this thread's 2 channels

    const float* fb = feat + ((size_t)n * C_ + cbase) * HW_;

    ull  acc[2][K_];
    ull  sum2[2];
    float vmax[2];
    #pragma unroll
    for (int ch = 0; ch < 2; ch++) {
        #pragma unroll
        for (int k = 0; k < K_; k++) acc[ch][k] = 0ull;   // (+0.0f, +0.0f)
        sum2[ch] = 0ull;
        vmax[ch] = -3.402823466e+38f;
    }

    #pragma unroll
    for (int j = 0; j < 4; j++) {
        const int p = j * 32 + o * 4;     // this lane's 4 positions this step

        float4 f[2];
        #pragma unroll
        for (int ch = 0; ch < 2; ch++)
            f[ch] = *reinterpret_cast<const float4*>(fb + ch * HW_ + p);

        ull fxy[2], fzw[2];
        #pragma unroll
        for (int ch = 0; ch < 2; ch++) {
            fxy[ch] = pack2(f[ch].x, f[ch].y);
            fzw[ch] = pack2(f[ch].z, f[ch].w);
            sum2[ch] = add2(sum2[ch], add2(fxy[ch], fzw[ch]));
            vmax[ch] = fmaxf(vmax[ch], fmaxf(fmaxf(f[ch].x, f[ch].y),
                                             fmaxf(f[ch].z, f[ch].w)));
        }

        #pragma unroll
        for (int k = 0; k < K_; k++) {
            // one LDS.128: scoremap[k, p..p+3] -> two packed f32x2 operands
            const ulonglong2 s2 =
                *reinterpret_cast<const ulonglong2*>(s_s + k * HW_ + p);
            #pragma unroll
            for (int ch = 0; ch < 2; ch++) {
                acc[ch][k] = fma2(fxy[ch], s2.x, acc[ch][k]);
                acc[ch][k] = fma2(fzw[ch], s2.y, acc[ch][k]);
            }
        }
    }

    // octet reduction (lanes differ in lane-id bits 0..2) + writeout
    const unsigned mask = 0xffffffffu;
    #pragma unroll
    for (int ch = 0; ch < 2; ch++) {
        float res[K_];
        #pragma unroll
        for (int k = 0; k < K_; k++) {
            float lo, hi; unpack2(acc[ch][k], lo, hi);
            res[k] = lo + hi;
        }
        float lo, hi; unpack2(sum2[ch], lo, hi);
        float sm = lo + hi;
        float mx = vmax[ch];

        #pragma unroll
        for (int d = 1; d < 8; d <<= 1) {
            #pragma unroll
            for (int k = 0; k < K_; k++)
                res[k] += __shfl_xor_sync(mask, res[k], d);
            sm += __shfl_xor_sync(mask, sm, d);
            mx  = fmaxf(mx, __shfl_xor_sync(mask, mx, d));
        }

        if (o == 0) {
            const int c = cbase + ch;
            float* ob = out + (size_t)n * 14 * C_ + c;
            #pragma unroll
            for (int k = 0; k < K_; k++) ob[(size_t)k * C_] = res[k];
            ob[(size_t)13 * C_] = sm * (1.0f / 128.0f) + mx;
        }
    }
}

extern "C" void kernel_launch(void* const* d_in, const int* in_sizes, int n_in,
                              void* d_out, int out_size)
{
    const float* feat = (const float*)d_in[0];           // [256,2048,16,8]
    const float* sc   = (const float*)d_in[1];           // [256,13,16,8]
    const float* kc   = (const float*)d_in[2];           // [256,13]
    float* out = (float*)d_out;

    dim3 grid(C_ / 32, N_);                               // 64 x 256 blocks
    fused_local_global_kernel<<<grid, 128>>>(feat, sc, kc, out, out_size);
}

// round 9
// speedup vs baseline: 1.3099x; 1.0026x over previous
#include <cuda_runtime.h>
#include <cstdint>

#define N_   256
#define C_   2048
#define HW_  128
#define K_   13

typedef unsigned long long ull;

// ---------- packed f32x2 helpers (sm_103a) ----------
__device__ __forceinline__ ull pack2(float lo, float hi) {
    ull r; asm("mov.b64 %0, {%1,%2};" : "=l"(r) : "f"(lo), "f"(hi)); return r;
}
__device__ __forceinline__ void unpack2(ull v, float& lo, float& hi) {
    asm("mov.b64 {%0,%1}, %2;" : "=f"(lo), "=f"(hi) : "l"(v));
}
__device__ __forceinline__ ull fma2(ull a, ull b, ull c) {
    ull d; asm("fma.rn.f32x2 %0, %1, %2, %3;" : "=l"(d) : "l"(a), "l"(b), "l"(c)); return d;
}
__device__ __forceinline__ ull add2(ull a, ull b) {
    ull d; asm("add.rn.f32x2 %0, %1, %2;" : "=l"(d) : "l"(a), "l"(b)); return d;
}

// Fused: local[n,k,c] = sum_hw scoremap[n,k,hw]*feat[n,c,hw]
//        glob[n,c]    = mean_hw feat + max_hw feat
//        conf[n,:]    = [L1norm(kc[n]), 1.0]
// Output: feat_vecs [N,14,C] row-major, then conf [N,14].
//
// 2 channels/thread, octet coalescing. ALL 8 feat LDG.128 hoisted to
// registers up-front (MLP=8: one exposed DRAM stall per warp, not two).
// Dual-channel packed reduction + STG.64 writeout.
__global__ void __launch_bounds__(128, 5)
fused_local_global_kernel(const float* __restrict__ feat,
                          const float* __restrict__ scoremap,
                          const float* __restrict__ kc,
                          float* __restrict__ out,
                          int out_size)
{
    __shared__ __align__(16) float s_s[K_ * HW_];   // scoremap[n] : 13 x 128

    const int n   = blockIdx.y;
    const int c0  = blockIdx.x * 32;                // 32 channels per block
    const int tid = threadIdx.x;

    // conf for this n (warp 0 of blockIdx.x==0 blocks). Full-warp shuffle.
    if (blockIdx.x == 0 && tid < 32) {
        const float v = (tid < K_) ? kc[n * K_ + tid] : 0.0f;
        float s = fabsf(v);
        #pragma unroll
        for (int d = 1; d < 32; d <<= 1)
            s += __shfl_xor_sync(0xffffffffu, s, d);
        const float inv = 1.0f / fmaxf(s, 1e-12f);
        const long long base = (long long)N_ * 14 * C_ + (long long)n * 14;
        if (tid < 14 && base + 14 <= (long long)out_size)
            out[base + tid] = (tid < K_) ? v * inv : 1.0f;
    }

    // stage scoremap[n] (6.5 KB) into smem
    {
        const float4* src = reinterpret_cast<const float4*>(scoremap + (size_t)n * K_ * HW_);
        float4* dst = reinterpret_cast<float4*>(s_s);
        for (int i = tid; i < K_ * HW_ / 4; i += 128) dst[i] = src[i];
    }

    const int o = tid & 7;        // lane within octet -> spatial sub-slice
    const int g = tid >> 3;       // octet index within block (0..15)
    const int cbase = c0 + g * 2; // this thread's 2 channels (even base)

    const float* fb = feat + ((size_t)n * C_ + cbase) * HW_;

    // hoist ALL feat loads (8 x LDG.128, issued before the syncthreads wait)
    float4 f[2][4];
    #pragma unroll
    for (int j = 0; j < 4; j++) {
        const int p = j * 32 + o * 4;
        #pragma unroll
        for (int ch = 0; ch < 2; ch++)
            f[ch][j] = *reinterpret_cast<const float4*>(fb + ch * HW_ + p);
    }

    __syncthreads();

    ull  acc[2][K_];
    ull  sum2[2];
    float vmax[2];
    #pragma unroll
    for (int ch = 0; ch < 2; ch++) {
        #pragma unroll
        for (int k = 0; k < K_; k++) acc[ch][k] = 0ull;   // (+0.0f, +0.0f)
        sum2[ch] = 0ull;
        vmax[ch] = -3.402823466e+38f;
    }

    #pragma unroll
    for (int j = 0; j < 4; j++) {
        const int p = j * 32 + o * 4;

        ull fxy[2], fzw[2];
        #pragma unroll
        for (int ch = 0; ch < 2; ch++) {
            const float4 fv = f[ch][j];
            fxy[ch] = pack2(fv.x, fv.y);
            fzw[ch] = pack2(fv.z, fv.w);
            sum2[ch] = add2(sum2[ch], add2(fxy[ch], fzw[ch]));
            vmax[ch] = fmaxf(vmax[ch], fmaxf(fmaxf(fv.x, fv.y),
                                             fmaxf(fv.z, fv.w)));
        }

        #pragma unroll
        for (int k = 0; k < K_; k++) {
            // one LDS.128: scoremap[k, p..p+3] -> two packed f32x2 operands
            const ulonglong2 s2 =
                *reinterpret_cast<const ulonglong2*>(s_s + k * HW_ + p);
            #pragma unroll
            for (int ch = 0; ch < 2; ch++) {
                acc[ch][k] = fma2(fxy[ch], s2.x, acc[ch][k]);
                acc[ch][k] = fma2(fzw[ch], s2.y, acc[ch][k]);
            }
        }
    }

    // dual-channel packed reduction: accp[k] = (res_ch0[k], res_ch1[k])
    ull accp[K_];
    #pragma unroll
    for (int k = 0; k < K_; k++) {
        float l0, h0, l1, h1;
        unpack2(acc[0][k], l0, h0);
        unpack2(acc[1][k], l1, h1);
        accp[k] = pack2(l0 + h0, l1 + h1);
    }
    float s0l, s0h, s1l, s1h;
    unpack2(sum2[0], s0l, s0h);
    unpack2(sum2[1], s1l, s1h);
    ull g2 = pack2(s0l + s0h, s1l + s1h);
    float mx0 = vmax[0], mx1 = vmax[1];

    const unsigned mask = 0xffffffffu;
    #pragma unroll
    for (int d = 1; d < 8; d <<= 1) {
        #pragma unroll
        for (int k = 0; k < K_; k++)
            accp[k] = add2(accp[k], __shfl_xor_sync(mask, accp[k], d));
        g2  = add2(g2, __shfl_xor_sync(mask, g2, d));
        mx0 = fmaxf(mx0, __shfl_xor_sync(mask, mx0, d));
        mx1 = fmaxf(mx1, __shfl_xor_sync(mask, mx1, d));
    }

    if (o == 0) {
        float* ob = out + (size_t)n * 14 * C_ + cbase;   // cbase even -> 8B aligned
        #pragma unroll
        for (int k = 0; k < K_; k++)
            *reinterpret_cast<ull*>(ob + (size_t)k * C_) = accp[k];
        float gl, gh; unpack2(g2, gl, gh);
        *reinterpret_cast<ull*>(ob + (size_t)13 * C_) =
            pack2(gl * (1.0f / 128.0f) + mx0, gh * (1.0f / 128.0f) + mx1);
    }
}

extern "C" void kernel_launch(void* const* d_in, const int* in_sizes, int n_in,
                              void* d_out, int out_size)
{
    const float* feat = (const float*)d_in[0];           // [256,2048,16,8]
    const float* sc   = (const float*)d_in[1];           // [256,13,16,8]
    const float* kc   = (const float*)d_in[2];           // [256,13]
    float* out = (float*)d_out;

    dim3 grid(C_ / 32, N_);                               // 64 x 256 blocks
    fused_local_global_kernel<<<grid, 128>>>(feat, sc, kc, out, out_size);
}

// round 15
// speedup vs baseline: 1.9713x; 1.5050x over previous
#include <cuda_runtime.h>
#include <cstdint>

#define N_   256
#define C_   2048
#define HW_  128
#define K_   13
#define KP_  7            // ceil(13/2) k-pairs, pair 6 hi lane = zero pad
#define KPS_ 128          // ulls per kp row (64 16B-units, XOR-swizzled)

typedef unsigned long long ull;

// ---------- packed f32x2 helpers (sm_103a) ----------
__device__ __forceinline__ ull pack2(float lo, float hi) {
    ull r; asm("mov.b64 %0, {%1,%2};" : "=l"(r) : "f"(lo), "f"(hi)); return r;
}
__device__ __forceinline__ void unpack2(ull v, float& lo, float& hi) {
    asm("mov.b64 {%0,%1}, %2;" : "=f"(lo), "=f"(hi) : "l"(v));
}
__device__ __forceinline__ ull fma2(ull a, ull b, ull c) {
    ull d; asm("fma.rn.f32x2 %0, %1, %2, %3;" : "=l"(d) : "l"(a), "l"(b), "l"(c)); return d;
}
__device__ __forceinline__ ull add2(ull a, ull b) {
    ull d; asm("add.rn.f32x2 %0, %1, %2;" : "=l"(d) : "l"(a), "l"(b)); return d;
}
// XOR swizzle on 16B-unit index: bijection; makes the octet LDS.128 pattern
// (lanes o=0..7, units u = j*16 + o*2 + pp) cover all 32 banks.
__device__ __forceinline__ int swz(int u) { return u ^ ((u >> 3) & 1); }

// Fused: local[n,k,c] = sum_hw scoremap[n,k,hw]*feat[n,c,hw]
//        glob[n,c]    = mean + max over hw
//        conf[n,:]    = [L1norm(kc[n]), 1.0]
//
// k-pair packed accumulators: acc[ch][kp] = (sum f*s[2kp], sum f*s[2kp+1]).
// Scoremap stored k-pair interleaved: 16B unit = (s[2kp][p],s[2kp+1][p],
// s[2kp][p+1],s[2kp+1][p+1]) at XOR-swizzled unit index. 4 channels/thread
// halves per-channel LDS traffic vs 2ch (attacks the measured 69% L1 pipe).
__global__ void __launch_bounds__(128, 4)
fused_local_global_kernel(const float* __restrict__ feat,
                          const float* __restrict__ scoremap,
                          const float* __restrict__ kc,
                          float* __restrict__ out,
                          int out_size)
{
    __shared__ __align__(16) ull s_i[KP_ * KPS_];   // 7168 B interleaved

    const int n   = blockIdx.y;
    const int c0  = blockIdx.x * 64;                // 64 channels per block
    const int tid = threadIdx.x;

    // conf for this n (warp 0 of blockIdx.x==0 blocks). Full-warp shuffle.
    if (blockIdx.x == 0 && tid < 32) {
        const float v = (tid < K_) ? kc[n * K_ + tid] : 0.0f;
        float s = fabsf(v);
        #pragma unroll
        for (int d = 1; d < 32; d <<= 1)
            s += __shfl_xor_sync(0xffffffffu, s, d);
        const float inv = 1.0f / fmaxf(s, 1e-12f);
        const long long base = (long long)N_ * 14 * C_ + (long long)n * 14;
        if (tid < 14 && base + 14 <= (long long)out_size)
            out[base + tid] = (tid < K_) ? v * inv : 1.0f;
    }

    // stage scoremap[n] interleaved by k-pair; tid = position p.
    // ull for position p of row r lives at r*KPS_ + 2*swz(p>>1) + (p&1).
    {
        const float* g_sc = scoremap + (size_t)n * K_ * HW_;
        const int idx = 2 * swz(tid >> 1) + (tid & 1);
        #pragma unroll
        for (int r = 0; r < KP_; r++) {
            const float lo = g_sc[(2 * r) * HW_ + tid];
            const float hi = (2 * r + 1 < K_) ? g_sc[(2 * r + 1) * HW_ + tid] : 0.0f;
            s_i[r * KPS_ + idx] = pack2(lo, hi);
        }
    }
    __syncthreads();

    const int o = tid & 7;        // lane within octet -> spatial sub-slice
    const int g = tid >> 3;       // octet index within block (0..15)
    const int cbase = c0 + g * 4; // this thread's 4 channels

    const float* fb = feat + ((size_t)n * C_ + cbase) * HW_;

    ull  acc[4][KP_];
    ull  sum2[4];
    float vmax[4];
    #pragma unroll
    for (int ch = 0; ch < 4; ch++) {
        #pragma unroll
        for (int kp = 0; kp < KP_; kp++) acc[ch][kp] = 0ull;
        sum2[ch] = 0ull;
        vmax[ch] = -3.402823466e+38f;
    }

    #pragma unroll
    for (int j = 0; j < 4; j++) {
        const int p0 = j * 32 + o * 4;

        float4 f[4];
        #pragma unroll
        for (int ch = 0; ch < 4; ch++)
            f[ch] = *reinterpret_cast<const float4*>(fb + ch * HW_ + p0);

        #pragma unroll
        for (int ch = 0; ch < 4; ch++) {
            sum2[ch] = add2(sum2[ch], add2(pack2(f[ch].x, f[ch].y),
                                           pack2(f[ch].z, f[ch].w)));
            vmax[ch] = fmaxf(vmax[ch], fmaxf(fmaxf(f[ch].x, f[ch].y),
                                             fmaxf(f[ch].z, f[ch].w)));
        }

        #pragma unroll
        for (int pp = 0; pp < 2; pp++) {
            // unit covering positions p0+2pp, p0+2pp+1
            const int uoff = 2 * swz(j * 16 + o * 2 + pp);

            ull fdA[4], fdB[4];
            #pragma unroll
            for (int ch = 0; ch < 4; ch++) {
                const float a = (&f[ch].x)[2 * pp];
                const float b = (&f[ch].x)[2 * pp + 1];
                fdA[ch] = pack2(a, a);
                fdB[ch] = pack2(b, b);
            }
            #pragma unroll
            for (int kp = 0; kp < KP_; kp++) {
                const ulonglong2 s2 =
                    *reinterpret_cast<const ulonglong2*>(s_i + kp * KPS_ + uoff);
                #pragma unroll
                for (int ch = 0; ch < 4; ch++) {
                    acc[ch][kp] = fma2(fdA[ch], s2.x, acc[ch][kp]);
                    acc[ch][kp] = fma2(fdB[ch], s2.y, acc[ch][kp]);
                }
            }
        }
    }

    // global-branch per-channel scalars
    float gsum[4];
    #pragma unroll
    for (int ch = 0; ch < 4; ch++) {
        float lo, hi; unpack2(sum2[ch], lo, hi);
        gsum[ch] = lo + hi;
    }

    // octet butterfly (lanes differ in bits 0..2 of lane id)
    const unsigned mask = 0xffffffffu;
    ull gp01 = pack2(gsum[0], gsum[1]);
    ull gp23 = pack2(gsum[2], gsum[3]);
    #pragma unroll
    for (int d = 1; d < 8; d <<= 1) {
        #pragma unroll
        for (int ch = 0; ch < 4; ch++)
            #pragma unroll
            for (int kp = 0; kp < KP_; kp++)
                acc[ch][kp] = add2(acc[ch][kp], __shfl_xor_sync(mask, acc[ch][kp], d));
        gp01 = add2(gp01, __shfl_xor_sync(mask, gp01, d));
        gp23 = add2(gp23, __shfl_xor_sync(mask, gp23, d));
        #pragma unroll
        for (int ch = 0; ch < 4; ch++)
            vmax[ch] = fmaxf(vmax[ch], __shfl_xor_sync(mask, vmax[ch], d));
    }

    if (o == 0) {
        float gs[4];
        unpack2(gp01, gs[0], gs[1]);
        unpack2(gp23, gs[2], gs[3]);
        #pragma unroll
        for (int ch = 0; ch < 4; ch++) {
            const int c = cbase + ch;
            float* ob = out + (size_t)n * 14 * C_ + c;
            #pragma unroll
            for (int kp = 0; kp < KP_; kp++) {
                float lo, hi; unpack2(acc[ch][kp], lo, hi);
                ob[(size_t)(2 * kp) * C_] = lo;
                if (2 * kp + 1 < K_) ob[(size_t)(2 * kp + 1) * C_] = hi;
            }
            ob[(size_t)13 * C_] = gs[ch] * (1.0f / 128.0f) + vmax[ch];
        }
    }
}

extern "C" void kernel_launch(void* const* d_in, const int* in_sizes, int n_in,
                              void* d_out, int out_size)
{
    const float* feat = (const float*)d_in[0];           // [256,2048,16,8]
    const float* sc   = (const float*)d_in[1];           // [256,13,16,8]
    const float* kc   = (const float*)d_in[2];           // [256,13]
    float* out = (float*)d_out;

    dim3 grid(C_ / 64, N_);                               // 32 x 256 blocks
    fused_local_global_kernel<<<grid, 128>>>(feat, sc, kc, out, out_size);
}